// round 4
// baseline (speedup 1.0000x reference)
#include <cuda_runtime.h>
#include <math.h>

// ---------------------------------------------------------------------------
// EASeq2SeqLSTM: B=256, L=365, F=32, S=27, H=256, HOR=24, NT=1
//
// Persistent single-kernel design: 128 CTAs (all co-resident, 1/SM), custom
// grid barrier, one barrier per recurrent step. Each CTA owns a 32(batch) x
// 16(hidden) tile of the state. Gate columns are packed as col = hidx*4+gate
// so each thread's 4 accumulator columns are the 4 gates of ONE hidden unit
// -> cell update is fully in-register, no cross-CTA gate exchange.
// ---------------------------------------------------------------------------

#define LSEQ  365
#define BATCH 256
#define FDIM  32
#define SDIM  27
#define HDIM  256
#define HORZ  24
#define NBLK  128
#define NTHR  256
#define GSTRIDE (NBLK * NTHR)

// ------------------------- device scratch (static) -------------------------
__device__ float g_easeq[(size_t)LSEQ * BATCH * HDIM];   // 95.6 MB
__device__ float g_h0[BATCH * HDIM];
__device__ float g_h1[BATCH * HDIM];
__device__ float g_c [BATCH * HDIM];
__device__ float g_cA[BATCH * HDIM];
__device__ float g_cB[BATCH * HDIM];
__device__ float g_hc0[BATCH * 512];    // decoder concat(hA, hB) ping
__device__ float g_hc1[BATCH * 512];    // decoder concat(hA, hB) pong
__device__ float g_si[BATCH * HDIM];
__device__ float g_sg[BATCH * HDIM];
__device__ __align__(16) float g_Bea [288 * 1024];  // EA packed weights  [K][col]
__device__ __align__(16) float g_Benc[512 * 1024];  // enc packed weights
__device__ __align__(16) float g_Bd0 [256 * 1024];  // dec layer0 packed
__device__ __align__(16) float g_Bd1 [512 * 1024];  // dec layer1 packed
__device__ __align__(16) float g_bEA [1024];
__device__ __align__(16) float g_bENC[1024];
__device__ __align__(16) float g_bD0 [1024];
__device__ __align__(16) float g_bD1 [1024];
__device__ __align__(16) float g_w0  [1024];        // dec_Wih0 packed
__device__ float g_din[BATCH];
__device__ unsigned int g_count = 0;
__device__ unsigned int g_gen   = 0;

// ------------------------------ grid barrier -------------------------------
__device__ __forceinline__ void gridsync()
{
    __syncthreads();
    if (threadIdx.x == 0) {
        __threadfence();
        unsigned int target = *((volatile unsigned int*)&g_gen) + 1u;
        if (atomicAdd(&g_count, 1u) == NBLK - 1u) {
            atomicExch(&g_count, 0u);
            __threadfence();
            atomicExch(&g_gen, target);
        } else {
            while ((int)(*((volatile unsigned int*)&g_gen) - target) < 0) { }
        }
        __threadfence();
    }
    __syncthreads();
}

__device__ __forceinline__ float sigm(float v) { return 1.0f / (1.0f + expf(-v)); }

// ------------------------------- GEMM tile ---------------------------------
// C[32 x 64] += A[32 x K] * B[K x 64], K = nkb*32. A fed by lambda, B from a
// packed [K][1024] global at column offset ct*64. Double-buffered smem, regs
// prefetch. Thread (tx,ty): rows {ty*2, ty*2+1}, cols {tx*4 .. tx*4+3}.
template <class AF>
__device__ __forceinline__ void gemm_run(float (&acc)[2][4], int nkb, AF Aload,
                                         const float* __restrict__ Bg,
                                         int ct, int tid, float* sA, float* sB)
{
    const int akk = tid & 31, arr = tid >> 5;   // A loader: k, row-base
    const int bcc = tid & 63, bk0 = tid >> 6;   // B loader: col, k-base
    const int tx  = tid & 15, ty  = tid >> 4;
    const float* bptr = Bg + ct * 64 + bcc;
    float ra[4], rb[8];

#pragma unroll
    for (int p = 0; p < 4; p++) ra[p] = Aload(akk, arr + p * 8);
#pragma unroll
    for (int p = 0; p < 8; p++) rb[p] = bptr[(bk0 + p * 4) * 1024];

    int buf = 0;
#pragma unroll
    for (int p = 0; p < 4; p++) sA[akk * 34 + arr + p * 8] = ra[p];
#pragma unroll
    for (int p = 0; p < 8; p++) sB[(bk0 + p * 4) * 64 + bcc] = rb[p];
    __syncthreads();

    for (int kb = 0; kb < nkb; kb++) {
        const bool more = (kb + 1 < nkb);
        if (more) {
            const int kg = (kb + 1) * 32;
#pragma unroll
            for (int p = 0; p < 4; p++) ra[p] = Aload(kg + akk, arr + p * 8);
#pragma unroll
            for (int p = 0; p < 8; p++) rb[p] = bptr[(kg + bk0 + p * 4) * 1024];
        }
        const float* A_ = sA + buf * 1088;
        const float* B_ = sB + buf * 2048;
#pragma unroll
        for (int kk = 0; kk < 32; kk++) {
            float2 a  = *(const float2*)(A_ + kk * 34 + ty * 2);
            float4 b4 = *(const float4*)(B_ + kk * 64 + tx * 4);
            acc[0][0] += a.x * b4.x; acc[0][1] += a.x * b4.y;
            acc[0][2] += a.x * b4.z; acc[0][3] += a.x * b4.w;
            acc[1][0] += a.y * b4.x; acc[1][1] += a.y * b4.y;
            acc[1][2] += a.y * b4.z; acc[1][3] += a.y * b4.w;
        }
        if (more) {
            const int nb = buf ^ 1;
            float* An = sA + nb * 1088;
            float* Bn = sB + nb * 2048;
#pragma unroll
            for (int p = 0; p < 4; p++) An[akk * 34 + arr + p * 8] = ra[p];
#pragma unroll
            for (int p = 0; p < 8; p++) Bn[(bk0 + p * 4) * 64 + bcc] = rb[p];
        }
        __syncthreads();
        buf ^= 1;
    }
}

// --------------------------------- kernel ----------------------------------
__global__ void __launch_bounds__(NTHR, 1)
ea_seq2seq_kernel(const float* __restrict__ x,    const float* __restrict__ s,
                  const float* __restrict__ Wf,   const float* __restrict__ bf,
                  const float* __restrict__ Wo,   const float* __restrict__ bo,
                  const float* __restrict__ Wi,   const float* __restrict__ bi,
                  const float* __restrict__ Wg,   const float* __restrict__ bg,
                  const float* __restrict__ Wsi,  const float* __restrict__ bsi,
                  const float* __restrict__ Wsg,  const float* __restrict__ bsg,
                  const float* __restrict__ eWih, const float* __restrict__ eWhh,
                  const float* __restrict__ ebih, const float* __restrict__ ebhh,
                  const float* __restrict__ dWih0,const float* __restrict__ dWhh0,
                  const float* __restrict__ dbih0,const float* __restrict__ dbhh0,
                  const float* __restrict__ dWih1,const float* __restrict__ dWhh1,
                  const float* __restrict__ dbih1,const float* __restrict__ dbhh1,
                  const float* __restrict__ fcW,  const float* __restrict__ fcb,
                  float* __restrict__ out)
{
    __shared__ __align__(16) float sA[2 * 1088];
    __shared__ __align__(16) float sB[2 * 2048];
    __shared__ float sred[8];

    const int tid  = threadIdx.x;
    const int bid  = blockIdx.x;
    const int gtid = bid * NTHR + tid;
    const int tx   = tid & 15, ty = tid >> 4;
    const int rt   = bid >> 4, ct = bid & 15;
    const int r0   = rt * 32;            // batch rows [r0, r0+32)
    const int hidx = ct * 16 + tx;       // hidden unit owned by this thread
    const int col0 = ct * 64 + tx * 4;   // packed gate-column base
    const int row0 = r0 + ty * 2;

    // ---------------- prep: pack weights, biases, si/sg, zero state --------
    // EA: gates f,o,i,g at col = h*4 + g. K: [0,256) = h-part, [256,288) = x-part
    for (int i = gtid; i < 288 * 1024; i += GSTRIDE) {
        int k = i >> 10, col = i & 1023, h = col >> 2, g = col & 3;
        const float* W = (g == 0) ? Wf : (g == 1) ? Wo : (g == 2) ? Wi : Wg;
        g_Bea[i] = (k < 256) ? W[h * 288 + 32 + k] : W[h * 288 + (k - 256)];
    }
    // enc: torch gate order i,f,g,o; K: [0,256) = Wih (input = ea_seq), [256,512) = Whh
    for (int i = gtid; i < 512 * 1024; i += GSTRIDE) {
        int k = i >> 10, col = i & 1023, n = (col & 3) * 256 + (col >> 2);
        g_Benc[i] = (k < 256) ? eWih[n * 256 + k] : eWhh[n * 256 + (k - 256)];
    }
    for (int i = gtid; i < 256 * 1024; i += GSTRIDE) {
        int k = i >> 10, col = i & 1023, n = (col & 3) * 256 + (col >> 2);
        g_Bd0[i] = dWhh0[n * 256 + k];
    }
    for (int i = gtid; i < 512 * 1024; i += GSTRIDE) {
        int k = i >> 10, col = i & 1023, n = (col & 3) * 256 + (col >> 2);
        g_Bd1[i] = (k < 256) ? dWih1[n * 256 + k] : dWhh1[n * 256 + (k - 256)];
    }
    for (int i = gtid; i < 1024; i += GSTRIDE) {
        int h = i >> 2, g = i & 3, n = g * 256 + h;
        g_bEA[i]  = ((g == 0) ? bf : (g == 1) ? bo : (g == 2) ? bi : bg)[h];
        g_bENC[i] = ebih[n] + ebhh[n];
        g_bD0[i]  = dbih0[n] + dbhh0[n];
        g_bD1[i]  = dbih1[n] + dbhh1[n];
        g_w0[i]   = dWih0[n];
    }
    for (int i = gtid; i < BATCH * HDIM; i += GSTRIDE) {
        int b = i >> 8, h = i & 255;
        float as = bsi[h], ag = bsg[h];
#pragma unroll
        for (int j = 0; j < SDIM; j++) {
            float sv = s[b * SDIM + j];
            as += sv * Wsi[h * SDIM + j];
            ag += sv * Wsg[h * SDIM + j];
        }
        g_si[i] = as; g_sg[i] = ag;
        g_h0[i] = 0.0f; g_c[i] = 0.0f;
    }
    gridsync();

    float* hin  = g_h0;
    float* hout = g_h1;

    // ---------------- EA loop (365 steps, K = 256(h) + 32(x)) --------------
    for (int t = 0; t < LSEQ; t++) {
        float acc[2][4];
        float4 bb = *(const float4*)&g_bEA[col0];
#pragma unroll
        for (int r = 0; r < 2; r++) {
            int b = row0 + r;
            acc[r][0] = bb.x; acc[r][1] = bb.y;
            acc[r][2] = bb.z + g_si[b * 256 + hidx];
            acc[r][3] = bb.w + g_sg[b * 256 + hidx];
        }
        auto ldA = [&](int kg, int row) -> float {
            int b = r0 + row;
            return (kg < 256) ? hin[b * 256 + kg]
                              : x[(b * LSEQ + t) * FDIM + (kg - 256)];
        };
        gemm_run(acc, 9, ldA, g_Bea, ct, tid, sA, sB);
#pragma unroll
        for (int r = 0; r < 2; r++) {
            int idx = (row0 + r) * 256 + hidx;
            float f = sigm(acc[r][0]), o = sigm(acc[r][1]);
            float ii = sigm(acc[r][2]), gg = tanhf(acc[r][3]);
            float c = f * g_c[idx] + ii * gg;
            float h = o * tanhf(c);
            g_c[idx] = c;
            hout[idx] = h;
            g_easeq[(size_t)t * (BATCH * HDIM) + idx] = h;
        }
        gridsync();
        float* tp = hin; hin = hout; hout = tp;
    }

    // ------------- encoder loop (365 steps, K = 256(ea_t) + 256(h)) --------
    for (int t = 0; t < LSEQ; t++) {
        float acc[2][4];
        float4 bb = *(const float4*)&g_bENC[col0];
#pragma unroll
        for (int r = 0; r < 2; r++) {
            acc[r][0] = bb.x; acc[r][1] = bb.y; acc[r][2] = bb.z; acc[r][3] = bb.w;
        }
        auto ldA = [&](int kg, int row) -> float {
            int b = r0 + row;
            return (kg < 256) ? g_easeq[(size_t)t * (BATCH * HDIM) + b * 256 + kg]
                              : hin[b * 256 + (kg - 256)];
        };
        gemm_run(acc, 16, ldA, g_Benc, ct, tid, sA, sB);
#pragma unroll
        for (int r = 0; r < 2; r++) {
            int idx = (row0 + r) * 256 + hidx;
            float ii = sigm(acc[r][0]), f = sigm(acc[r][1]);
            float gg = tanhf(acc[r][2]), o = sigm(acc[r][3]);
            float c = f * g_c[idx] + ii * gg;
            float h = o * tanhf(c);
            g_c[idx] = c;
            hout[idx] = h;
        }
        gridsync();
        float* tp = hin; hin = hout; hout = tp;
    }

    // ---------------- decoder init: hA=hB=h_enc, cA=cB=c_enc ---------------
    for (int i = gtid; i < BATCH * HDIM; i += GSTRIDE) {
        float hv = hin[i], cv = g_c[i];
        int b = i >> 8, h = i & 255;
        g_cA[i] = cv; g_cB[i] = cv;
        g_hc0[b * 512 + h]       = hv;   // hA
        g_hc0[b * 512 + 256 + h] = hv;   // hB
    }
    if (gtid < BATCH) g_din[gtid] = 0.0f;
    gridsync();

    float* hcin  = g_hc0;
    float* hcout = g_hc1;

    // ---------------- decoder loop (24 steps) ------------------------------
    for (int st = 0; st < HORZ; st++) {
        // layer 0: input = din scalar; K = 256 (hA)
        {
            float acc[2][4];
            float4 bb = *(const float4*)&g_bD0[col0];
            float4 w0 = *(const float4*)&g_w0[col0];
#pragma unroll
            for (int r = 0; r < 2; r++) {
                float d = g_din[row0 + r];
                acc[r][0] = bb.x + d * w0.x; acc[r][1] = bb.y + d * w0.y;
                acc[r][2] = bb.z + d * w0.z; acc[r][3] = bb.w + d * w0.w;
            }
            auto ldA = [&](int kg, int row) -> float {
                return hcin[(r0 + row) * 512 + kg];
            };
            gemm_run(acc, 8, ldA, g_Bd0, ct, tid, sA, sB);
#pragma unroll
            for (int r = 0; r < 2; r++) {
                int b = row0 + r;
                int idx = b * 256 + hidx;
                float ii = sigm(acc[r][0]), f = sigm(acc[r][1]);
                float gg = tanhf(acc[r][2]), o = sigm(acc[r][3]);
                float c = f * g_cA[idx] + ii * gg;
                float h = o * tanhf(c);
                g_cA[idx] = c;
                hcout[b * 512 + hidx] = h;   // hA (new)
            }
        }
        gridsync();
        // layer 1: K = 256 (hA new) + 256 (hB old)
        {
            float acc[2][4];
            float4 bb = *(const float4*)&g_bD1[col0];
#pragma unroll
            for (int r = 0; r < 2; r++) {
                acc[r][0] = bb.x; acc[r][1] = bb.y; acc[r][2] = bb.z; acc[r][3] = bb.w;
            }
            auto ldA = [&](int kg, int row) -> float {
                int b = r0 + row;
                return (kg < 256) ? hcout[b * 512 + kg]   // hA new
                                  : hcin[b * 512 + kg];   // hB old
            };
            gemm_run(acc, 16, ldA, g_Bd1, ct, tid, sA, sB);
#pragma unroll
            for (int r = 0; r < 2; r++) {
                int b = row0 + r;
                int idx = b * 256 + hidx;
                float ii = sigm(acc[r][0]), f = sigm(acc[r][1]);
                float gg = tanhf(acc[r][2]), o = sigm(acc[r][3]);
                float c = f * g_cB[idx] + ii * gg;
                float h = o * tanhf(c);
                g_cB[idx] = c;
                hcout[b * 512 + 256 + hidx] = h;  // hB (new)
            }
        }
        gridsync();
        // pred: out[b, st] = hB . fcW + fcb ; also feeds din for next step.
        {
            int bl = tid >> 7, kk = tid & 127;
            int b  = bid * 2 + bl;
            const float* hb = hcout + b * 512 + 256;
            float v = hb[kk] * fcW[kk] + hb[128 + kk] * fcW[128 + kk];
#pragma unroll
            for (int off = 16; off > 0; off >>= 1)
                v += __shfl_down_sync(0xffffffffu, v, off);
            if ((tid & 31) == 0) sred[tid >> 5] = v;
            __syncthreads();
            if (tid < 2) {
                float p = sred[tid * 4] + sred[tid * 4 + 1] +
                          sred[tid * 4 + 2] + sred[tid * 4 + 3] + fcb[0];
                int b2 = bid * 2 + tid;
                out[b2 * HORZ + st] = p;
                g_din[b2] = p;
            }
        }
        gridsync();
        float* tp = hcin; hcin = hcout; hcout = tp;
    }
}

// ------------------------------ launch shim --------------------------------
extern "C" void kernel_launch(void* const* d_in, const int* in_sizes, int n_in,
                              void* d_out, int out_size)
{
    (void)in_sizes; (void)n_in; (void)out_size;
    const float* p[28];
    for (int i = 0; i < 28; i++) p[i] = (const float*)d_in[i];
    ea_seq2seq_kernel<<<NBLK, NTHR>>>(
        p[0], p[1], p[2], p[3], p[4], p[5], p[6], p[7], p[8], p[9],
        p[10], p[11], p[12], p[13], p[14], p[15], p[16], p[17],
        p[18], p[19], p[20], p[21], p[22], p[23], p[24], p[25],
        p[26], p[27], (float*)d_out);
}